// round 15
// baseline (speedup 1.0000x reference)
#include <cuda_runtime.h>
#include <cuda_fp16.h>
#include <cstdint>
#include <cstddef>

// Problem constants
#define L_S_C   4096
#define QSTART  2048
#define L_NS_C  64
#define LQ      2112
#define LK      4160
#define DM      1024
#define NH      16
#define DH      64

// Q pre-scale: Dh^-0.5 * log2(e)  (softmax runs in exp2 domain)
#define QSC     0.18033688011f

// Scratch (device globals, fp16). g_Q padded +64 rows.
__device__ __align__(16) __half g_Q[(size_t)(LQ + 64) * DM];   // d 16-blk permuted, pre-scaled QSC
__device__ __align__(16) __half g_V[(size_t)LK * DM];          // plain [token][d]
__device__ __align__(16) __half g_AO[(size_t)LQ * DM];         // k 16-blk permuted
__device__ __align__(16) __half g_xr[(size_t)LK * DM];         // x, k 16-blk permuted
__device__ __align__(16) __half g_Wsr[(size_t)(3 * DM) * DM];  // W_S^T [n][k], permuted
__device__ __align__(16) __half g_Wor[(size_t)DM * DM];        // W_out^T [n][k], permuted
__device__ __align__(16) __half g_Kp[(size_t)LK * DM];         // K, d 16-blk permuted
__device__ __align__(16) __half g_Vt[(size_t)DM * LK];         // V^T [d][token], token permuted

// 16-block permutation: stored pos 4t..4t+3 hold orig k = 2t, 2t+1, 2t+8, 2t+9.
__device__ __forceinline__ int perm16(int c) {
    return (c < 8) ? (4 * (c >> 1) + (c & 1)) : (4 * ((c - 8) >> 1) + 2 + (c & 1));
}

__device__ __forceinline__ uint32_t h2u(float a, float b) {
    __half2 h = __floats2half2_rn(a, b);
    return *reinterpret_cast<uint32_t*>(&h);
}

__device__ __forceinline__ void mma16(float* c, const uint32_t* a, const uint32_t* b) {
    asm volatile(
        "mma.sync.aligned.m16n8k16.row.col.f32.f16.f16.f32 "
        "{%0,%1,%2,%3}, {%4,%5,%6,%7}, {%8,%9}, {%0,%1,%2,%3};\n"
        : "+f"(c[0]), "+f"(c[1]), "+f"(c[2]), "+f"(c[3])
        : "r"(a[0]), "r"(a[1]), "r"(a[2]), "r"(a[3]), "r"(b[0]), "r"(b[1]));
}

__device__ __forceinline__ void cp16(void* dst, const void* src, int sz) {
    uint32_t d = (uint32_t)__cvta_generic_to_shared(dst);
    asm volatile("cp.async.cg.shared.global [%0], [%1], 16, %2;\n"
                 :: "r"(d), "l"(src), "r"(sz));
}
#define CP_COMMIT()  asm volatile("cp.async.commit_group;\n")
#define CP_WAIT(n)   asm volatile("cp.async.wait_group %0;\n" :: "n"(n))

// ============================================================================
// Fused prep: blocks [0,3072) transpose W_S; [3072,4096) transpose W_out;
// [4096,4608) convert+permute x. All fp16 outputs, k 16-block permuted.
// ============================================================================
__global__ void __launch_bounds__(256)
prep_all(const float* __restrict__ x, const float* __restrict__ W_S,
         const float* __restrict__ W_out) {
    const int b = blockIdx.x;
    if (b < 4096) {
        __shared__ float t[32][33];
        const float* src;
        __half* dst;
        int C, c0, r0;
        if (b < 3072) { src = W_S;  dst = g_Wsr; C = 3 * DM;
                        c0 = (b % 96) * 32; r0 = (b / 96) * 32; }
        else          { int b2 = b - 3072; src = W_out; dst = g_Wor; C = DM;
                        c0 = (b2 % 32) * 32; r0 = (b2 / 32) * 32; }
        const int tx = threadIdx.x & 31, ty = threadIdx.x >> 5;
#pragma unroll
        for (int i = 0; i < 4; i++)
            t[ty + i * 8][tx] = src[(size_t)(r0 + ty + i * 8) * C + c0 + tx];
        __syncthreads();
        const int pk = r0 + (tx & ~15) + perm16(tx & 15);
#pragma unroll
        for (int i = 0; i < 4; i++)
            dst[(size_t)(c0 + ty + i * 8) * DM + pk] =
                __float2half_rn(t[tx][ty + i * 8]);
    } else {
        const int NB = (int)((size_t)LK * DM / 16);
        for (int i = (b - 4096) * 256 + threadIdx.x; i < NB; i += 512 * 256) {
            const float4* f = (const float4*)(x + (size_t)i * 16);
            float4 f0 = f[0], f1 = f[1], f2 = f[2], f3 = f[3];
            uint4 w0, w1;
            w0.x = h2u(f0.x, f0.y);  w0.y = h2u(f2.x, f2.y);
            w0.z = h2u(f0.z, f0.w);  w0.w = h2u(f2.z, f2.w);
            w1.x = h2u(f1.x, f1.y);  w1.y = h2u(f3.x, f3.y);
            w1.z = h2u(f1.z, f1.w);  w1.w = h2u(f3.z, f3.w);
            *(uint4*)&g_xr[(size_t)i * 16]     = w0;
            *(uint4*)&g_xr[(size_t)i * 16 + 8] = w1;
        }
    }
}

// V transpose repack: fp16 [d][token], token 16-block permuted.
__global__ void __launch_bounds__(256)
repack_Vt() {
    __shared__ __half t[32][34];
    const int tok0 = blockIdx.x * 32, d0 = blockIdx.y * 32;
    const int tx = threadIdx.x & 31, ty = threadIdx.x >> 5;
#pragma unroll
    for (int i = 0; i < 4; i++)
        t[ty + i * 8][tx] = g_V[(size_t)(tok0 + ty + i * 8) * DM + d0 + tx];
    __syncthreads();
    const int ptok = tok0 + (tx & ~15) + perm16(tx & 15);
#pragma unroll
    for (int i = 0; i < 4; i++)
        g_Vt[(size_t)(d0 + ty + i * 8) * LK + ptok] = t[tx][ty + i * 8];
}

// ============================================================================
// fp16 warp-MMA GEMM tile (m16n8k16): k-chunk 64, 3-buffer ring, prefetch
// distance 2 (CP_WAIT(1)), ONE barrier per iter. Stage s @ sm + s*18432
// halves (A 9216 + B 9216, stride 72). Total smem 110,592 B.
// MODE 0: scatter half2 into g_Q(scaled,perm)/g_Kp(perm)/g_V. MODE 1: store C.
// ============================================================================
template <int MODE>
__device__ __forceinline__ void gemm_tile(const __half* __restrict__ A,
                                          const __half* __restrict__ Bt,
                                          float* __restrict__ C,
                                          int M, int N, int Ks, int kBeg, int kLen,
                                          int mBase, int nBase, __half* sm) {
    const int tid  = threadIdx.x;
    const int warp = tid >> 5, lane = tid & 31;
    const int gid  = lane >> 2, tig = lane & 3;
    const int wm = (warp >> 2) * 64;
    const int wn = (warp & 3) * 32;

    float c[4][4][4];
#pragma unroll
    for (int i = 0; i < 4; i++)
#pragma unroll
        for (int j = 0; j < 4; j++)
#pragma unroll
            for (int e = 0; e < 4; e++) c[i][j][e] = 0.f;

    auto issue = [&](int k0, int s) {
        __half* As = sm + s * 18432;
        __half* Bs = As + 9216;
#pragma unroll
        for (int i = 0; i < 4; i++) {
            int ch  = tid + i * 256;        // 0..1023
            int row = ch >> 3;
            int cc  = (ch & 7) * 8;
            int grow = mBase + row;
            int ok = (MODE == 1) ? (grow < M) : 1;
            cp16(&As[row * 72 + cc], A + (size_t)(ok ? grow : 0) * Ks + k0 + cc,
                 ok ? 16 : 0);
            cp16(&Bs[row * 72 + cc], Bt + (size_t)(nBase + row) * Ks + k0 + cc, 16);
        }
        CP_COMMIT();
    };

    issue(kBeg, 0);
    issue(kBeg + 64, 1);

    const int T = kLen / 64;
    for (int t = 0; t < T; t++) {
        CP_WAIT(1);               // stage t complete (t+1 may be in flight)
        __syncthreads();          // all warps done reading stage t-1
        if (t + 2 < T) issue(kBeg + (t + 2) * 64, (t + 2) % 3);
        else CP_COMMIT();         // keep wait-group arithmetic aligned

        __half* As = sm + (t % 3) * 18432;
        __half* Bs = As + 9216;

#pragma unroll
        for (int ks = 0; ks < 4; ks++) {
            const int off = ks * 16 + 4 * tig;
            uint32_t a[4][4];
#pragma unroll
            for (int mt = 0; mt < 4; mt++) {
                int r = wm + mt * 16 + gid;
                uint2 u0 = *(const uint2*)&As[r * 72 + off];
                uint2 u1 = *(const uint2*)&As[(r + 8) * 72 + off];
                a[mt][0] = u0.x; a[mt][1] = u1.x; a[mt][2] = u0.y; a[mt][3] = u1.y;
            }
            uint32_t b[4][2];
#pragma unroll
            for (int nt = 0; nt < 4; nt++) {
                int rn = wn + nt * 8 + gid;
                uint2 v = *(const uint2*)&Bs[rn * 72 + off];
                b[nt][0] = v.x; b[nt][1] = v.y;
            }
#pragma unroll
            for (int mt = 0; mt < 4; mt++)
#pragma unroll
                for (int nt = 0; nt < 4; nt++)
                    mma16(c[mt][nt], a[mt], b[nt]);
        }
    }

#pragma unroll
    for (int mt = 0; mt < 4; mt++) {
#pragma unroll
        for (int nt = 0; nt < 4; nt++) {
            int row0 = mBase + wm + mt * 16 + gid;
            int row1 = row0 + 8;
            int col  = nBase + wn + nt * 8 + 2 * tig;
            float v0 = c[mt][nt][0], v1 = c[mt][nt][1];
            float v2 = c[mt][nt][2], v3 = c[mt][nt][3];
            if (MODE == 0) {
                if (col < DM) {
                    int db = col & ~15, p = perm16(col & 15);
                    if (row0 >= QSTART)
                        *(uint32_t*)&g_Q[(size_t)(row0 - QSTART) * DM + db + p] =
                            h2u(v0 * QSC, v1 * QSC);
                    if (row1 >= QSTART)
                        *(uint32_t*)&g_Q[(size_t)(row1 - QSTART) * DM + db + p] =
                            h2u(v2 * QSC, v3 * QSC);
                } else if (col < 2 * DM) {
                    int ck = col - DM;
                    int db = ck & ~15, p = perm16(ck & 15);
                    *(uint32_t*)&g_Kp[(size_t)row0 * DM + db + p] = h2u(v0, v1);
                    *(uint32_t*)&g_Kp[(size_t)row1 * DM + db + p] = h2u(v2, v3);
                } else {
                    int cv = col - 2 * DM;
                    *(uint32_t*)&g_V[(size_t)row0 * DM + cv] = h2u(v0, v1);
                    *(uint32_t*)&g_V[(size_t)row1 * DM + cv] = h2u(v2, v3);
                }
            } else {
                if (row0 < M) *(float2*)&C[(size_t)row0 * N + col] = make_float2(v0, v1);
                if (row1 < M) *(float2*)&C[(size_t)row1 * N + col] = make_float2(v2, v3);
            }
        }
    }
}

// ============================================================================
// Fused qkv: 640 live GEMM tiles + 192 NS streaming blocks (10:3 interleave).
// ============================================================================
extern __shared__ char dynsm[];

__global__ void __launch_bounds__(256, 2)
fused_qkv(const float* __restrict__ x, const float* __restrict__ W_NS) {
    const int bid = blockIdx.x;
    const int grp = bid / 13, rem = bid % 13;
    if (rem < 10) {
        const int g = grp * 10 + rem;       // 0..639
        int mt, nt;
        if (g < 384) { mt = 16 + g / 24; nt = g % 24; }            // rows>=2048: QKV
        else { int g2 = g - 384; mt = g2 / 16; nt = 8 + g2 % 16; } // rows<2048: KV only
        gemm_tile<0>((const __half*)g_xr, (const __half*)g_Wsr, nullptr,
                     4096, 3072, 1024, 0, 1024, mt * 128, nt * 128, (__half*)dynsm);
    } else {
        float* xs = (float*)dynsm;
        const int ns  = grp * 3 + (rem - 10);   // 0..191
        const int tok = ns / 3;
        const int cb  = ns % 3;                 // 0=Q, 1=K, 2=V
        const int c4  = cb * 1024 + threadIdx.x * 4;

        const float* xr = x + (size_t)(L_S_C + tok) * DM;
        for (int i = threadIdx.x; i < DM; i += 256) xs[i] = xr[i];
        __syncthreads();

        const float* Wp = W_NS + (size_t)tok * DM * 3072 + c4;
        float4 acc = make_float4(0.f, 0.f, 0.f, 0.f);
#pragma unroll 8
        for (int d = 0; d < DM; d++) {
            float4 w = __ldcs((const float4*)(Wp + (size_t)d * 3072));
            float xv = xs[d];
            acc.x = fmaf(xv, w.x, acc.x);
            acc.y = fmaf(xv, w.y, acc.y);
            acc.z = fmaf(xv, w.z, acc.z);
            acc.w = fmaf(xv, w.w, acc.w);
        }

        if (cb == 0) {
            int db = c4 & ~15, c16 = c4 & 15;
            __half* qd = g_Q + (size_t)(QSTART + tok) * DM + db;
            *(uint32_t*)&qd[perm16(c16)]     = h2u(acc.x * QSC, acc.y * QSC);
            *(uint32_t*)&qd[perm16(c16 + 2)] = h2u(acc.z * QSC, acc.w * QSC);
        } else if (cb == 1) {
            int ck = c4 - 1024;
            int db = ck & ~15, c16 = ck & 15;
            __half* kd = g_Kp + (size_t)(L_S_C + tok) * DM + db;
            *(uint32_t*)&kd[perm16(c16)]     = h2u(acc.x, acc.y);
            *(uint32_t*)&kd[perm16(c16 + 2)] = h2u(acc.z, acc.w);
        } else {
            uint2 w; w.x = h2u(acc.x, acc.y); w.y = h2u(acc.z, acc.w);
            *(uint2*)&g_V[(size_t)(L_S_C + tok) * DM + (c4 - 2048)] = w;
        }
    }
}

// Output projection: full K, direct stores.
__global__ void __launch_bounds__(256, 2)
gemm_out(float* __restrict__ C) {
    gemm_tile<1>((const __half*)g_AO, (const __half*)g_Wor, C, LQ, 1024, 1024,
                 0, 1024, blockIdx.y * 128, blockIdx.x * 128, (__half*)dynsm);
}

// ============================================================================
// Flash attention v9 (fp16): K double + V TRIPLE buffering -> ONE barrier per
// k-iter with a full-iteration prefetch window. 128 q-rows/CTA, 256 thr.
// Q frags in regs; P in registers; deferred-PV; l via ones-column MMA; exp2.
// smem: 2 K bufs + 3 V bufs = 5 x [64][72] halves = 46,080 B.
// ============================================================================
__global__ void __launch_bounds__(256, 2)
attn_kernel() {
    __half* Kb[2] = {(__half*)dynsm, (__half*)dynsm + 4608};
    __half* Vb[3] = {(__half*)dynsm + 9216, (__half*)dynsm + 13824,
                     (__half*)dynsm + 18432};

    const int qtp = 16 - ((int)blockIdx.x >> 4);   // descending work size
    const int h   = blockIdx.x & 15;
    const int qb  = qtp * 128;
    const int tid  = threadIdx.x;
    const int warp = tid >> 5, lane = tid & 31;
    const int gid  = lane >> 2, tig = lane & 3;
    const int rq0  = warp * 16 + gid;

    auto loadKV = [&](int kt) {
        __half* Kd = Kb[kt & 1];
        __half* Vd = Vb[kt % 3];
        const __half* kp = g_Kp + (size_t)kt * 64 * DM + h * DH;
        const __half* vp = g_Vt + (size_t)h * DH * LK + (size_t)kt * 64;
#pragma unroll
        for (int i = 0; i < 2; i++) {
            int ch = tid + i * 256;        // 0..511
            int r = ch >> 3, cc = (ch & 7) * 8;
            cp16(&Kd[r * 72 + cc], kp + (size_t)r * DM + cc, 16);
            cp16(&Vd[r * 72 + cc], vp + (size_t)r * LK + cc, 16);
        }
        CP_COMMIT();
    };

    loadKV(0);

    // Q fragments straight from gmem (pre-scaled, permuted).
    uint32_t qa[4][4];
    {
        const __half* q0 = g_Q + (size_t)(qb + rq0) * DM + h * DH;
        const __half* q1 = g_Q + (size_t)(qb + rq0 + 8) * DM + h * DH;
#pragma unroll
        for (int ks = 0; ks < 4; ks++) {
            uint2 u0 = *(const uint2*)(q0 + ks * 16 + 4 * tig);
            uint2 u1 = *(const uint2*)(q1 + ks * 16 + 4 * tig);
            qa[ks][0] = u0.x; qa[ks][1] = u1.x; qa[ks][2] = u0.y; qa[ks][3] = u1.y;
        }
    }

    float m0 = -1e30f, m1 = -1e30f;
    float sc0s = 0.f, sc1s = 0.f;
    uint32_t pa[4][4];                 // P(kt-1) as fp16 A-fragments
    const uint32_t oneb[2] = {0x3C003C00u, 0x3C003C00u};
    float ol[4] = {0.f, 0.f, 0.f, 0.f};   // l via ones-column MMA
    float o[8][4];
#pragma unroll
    for (int i = 0; i < 8; i++)
#pragma unroll
        for (int e = 0; e < 4; e++) o[i][e] = 0.f;

    const int nktFull = 34 + 2 * qtp;
    const int nkt = nktFull < 65 ? nktFull : 65;
    for (int kt = 0; kt < nkt; kt++) {
        CP_WAIT(0);               // K(kt), V(kt) landed (issued one iter ago)
        __syncthreads();          // all warps finished iter kt-1 reads
        if (kt + 1 < nkt) loadKV(kt + 1);   // overwrites K(kt-1)/V(kt-2): safe

        __half* Ks = Kb[kt & 1];

        // ---- S(kt) = Q @ K^T (exp2 domain) ----
        float s[8][4];
#pragma unroll
        for (int i = 0; i < 8; i++)
#pragma unroll
            for (int e = 0; e < 4; e++) s[i][e] = 0.f;

#pragma unroll
        for (int ks = 0; ks < 4; ks++) {
            const int off = ks * 16 + 4 * tig;
#pragma unroll
            for (int nt = 0; nt < 8; nt++) {
                uint2 kv = *(const uint2*)&Ks[(nt * 8 + gid) * 72 + off];
                uint32_t bb[2] = {kv.x, kv.y};
                mma16(s[nt], qa[ks], bb);
            }
        }

        // ---- deferred PV(kt-1): O = O*sc + P@V; l likewise via ones-MMA ----
        if (kt > 0) {
            __half* Vp = Vb[(kt - 1) % 3];
#pragma unroll
            for (int dt = 0; dt < 8; dt++) {
                o[dt][0] *= sc0s; o[dt][1] *= sc0s;
                o[dt][2] *= sc1s; o[dt][3] *= sc1s;
            }
            ol[0] *= sc0s; ol[1] *= sc0s; ol[2] *= sc1s; ol[3] *= sc1s;
#pragma unroll
            for (int g = 0; g < 4; g++) {
                const int off = g * 16 + 4 * tig;
#pragma unroll
                for (int dt = 0; dt < 8; dt++) {
                    uint2 vv = *(const uint2*)&Vp[(dt * 8 + gid) * 72 + off];
                    uint32_t bb[2] = {vv.x, vv.y};
                    mma16(o[dt], pa[g], bb);
                }
                mma16(ol, pa[g], oneb);
            }
        }

        // ---- causal mask on last two k-tiles ----
        if (kt >= nkt - 2) {
            const int off = kt * 64 - QSTART - qb;
#pragma unroll
            for (int nt = 0; nt < 8; nt++) {
#pragma unroll
                for (int e = 0; e < 4; e++) {
                    int kc  = nt * 8 + 2 * tig + (e & 1);
                    int rit = warp * 16 + gid + ((e >> 1) << 3);
                    if (kc + off > rit) s[nt][e] = -1e30f;
                }
            }
        }

        // ---- online softmax(kt): rowmax + exp2 (no sum reduction) ----
        float rm0 = -1e30f, rm1 = -1e30f;
#pragma unroll
        for (int nt = 0; nt < 8; nt++) {
            rm0 = fmaxf(rm0, fmaxf(s[nt][0], s[nt][1]));
            rm1 = fmaxf(rm1, fmaxf(s[nt][2], s[nt][3]));
        }
        rm0 = fmaxf(rm0, __shfl_xor_sync(0xffffffffu, rm0, 1));
        rm0 = fmaxf(rm0, __shfl_xor_sync(0xffffffffu, rm0, 2));
        rm1 = fmaxf(rm1, __shfl_xor_sync(0xffffffffu, rm1, 1));
        rm1 = fmaxf(rm1, __shfl_xor_sync(0xffffffffu, rm1, 2));

        float mn0 = fmaxf(m0, rm0), mn1 = fmaxf(m1, rm1);
        sc0s = exp2f(m0 - mn0);
        sc1s = exp2f(m1 - mn1);
        m0 = mn0; m1 = mn1;

        // ---- pack P(kt) = exp2(s - m) into register A-fragments ----
#pragma unroll
        for (int g = 0; g < 4; g++) {
            pa[g][0] = h2u(exp2f(s[2 * g][0] - m0),     exp2f(s[2 * g][1] - m0));
            pa[g][1] = h2u(exp2f(s[2 * g][2] - m1),     exp2f(s[2 * g][3] - m1));
            pa[g][2] = h2u(exp2f(s[2 * g + 1][0] - m0), exp2f(s[2 * g + 1][1] - m0));
            pa[g][3] = h2u(exp2f(s[2 * g + 1][2] - m1), exp2f(s[2 * g + 1][3] - m1));
        }
    }

    // ---- final deferred PV(nkt-1) ----
    {
        __half* Vp = Vb[(nkt - 1) % 3];
#pragma unroll
        for (int dt = 0; dt < 8; dt++) {
            o[dt][0] *= sc0s; o[dt][1] *= sc0s;
            o[dt][2] *= sc1s; o[dt][3] *= sc1s;
        }
        ol[0] *= sc0s; ol[1] *= sc0s; ol[2] *= sc1s; ol[3] *= sc1s;
#pragma unroll
        for (int g = 0; g < 4; g++) {
            const int off = g * 16 + 4 * tig;
#pragma unroll
            for (int dt = 0; dt < 8; dt++) {
                uint2 vv = *(const uint2*)&Vp[(dt * 8 + gid) * 72 + off];
                uint32_t bb[2] = {vv.x, vv.y};
                mma16(o[dt], pa[g], bb);
            }
            mma16(ol, pa[g], oneb);
        }
    }

    // Epilogue: g_AO fp16, k 16-block permuted (matches g_Wor).
    const float il0 = 1.f / ol[0], il1 = 1.f / ol[2];
    const int qr0 = qb + rq0, qr1 = qb + rq0 + 8;
#pragma unroll
    for (int dt = 0; dt < 8; dt++) {
        int col = h * DH + dt * 8 + 2 * tig;
        int db = col & ~15, p = perm16(col & 15);
        if (qr0 < LQ)
            *(uint32_t*)&g_AO[(size_t)qr0 * DM + db + p] =
                h2u(o[dt][0] * il0, o[dt][1] * il0);
        if (qr1 < LQ)
            *(uint32_t*)&g_AO[(size_t)qr1 * DM + db + p] =
                h2u(o[dt][2] * il1, o[dt][3] * il1);
    }
}

// ============================================================================
extern "C" void kernel_launch(void* const* d_in, const int* in_sizes, int n_in,
                              void* d_out, int out_size) {
    const float* x     = (const float*)d_in[0];
    const float* W_S   = (const float*)d_in[1];
    const float* W_NS  = (const float*)d_in[2];
    const float* W_out = (const float*)d_in[3];
    float* out = (float*)d_out;
    (void)in_sizes; (void)n_in; (void)out_size;

    const int gemm_smem = 3 * 18432 * 2;   // 110,592 B
    const int attn_smem = 5 * 4608 * 2;    // 46,080 B

    cudaFuncSetAttribute(fused_qkv,   cudaFuncAttributeMaxDynamicSharedMemorySize, gemm_smem);
    cudaFuncSetAttribute(gemm_out,    cudaFuncAttributeMaxDynamicSharedMemorySize, gemm_smem);
    cudaFuncSetAttribute(attn_kernel, cudaFuncAttributeMaxDynamicSharedMemorySize, attn_smem);

    // 0) fused prep: W_S / W_out transpose+permute, x convert+permute
    prep_all<<<4608, 256>>>(x, W_S, W_out);

    // 1+2) fused: live qkv GEMM tiles (640) + NS streaming (192)
    fused_qkv<<<832, 256, gemm_smem>>>(x, W_NS);

    // 2b) repack V (transpose + token 16-blk permute)
    repack_Vt<<<dim3(LK / 32, DM / 32), 256>>>();

    // 3) attention: 17 q-pair tiles x 16 heads, longest first
    attn_kernel<<<17 * NH, 256, attn_smem>>>();

    // 4) output projection, full K, direct stores
    gemm_out<<<dim3(1024 / 128, (LQ + 127) / 128), 256, gemm_smem>>>(out);
}

// round 16
// speedup vs baseline: 1.1687x; 1.1687x over previous
#include <cuda_runtime.h>
#include <cuda_fp16.h>
#include <cstdint>
#include <cstddef>

// Problem constants
#define L_S_C   4096
#define QSTART  2048
#define L_NS_C  64
#define LQ      2112
#define LK      4160
#define DM      1024
#define NH      16
#define DH      64

// Q pre-scale: Dh^-0.5 * log2(e)  (softmax runs in exp2 domain)
#define QSC     0.18033688011f

// Scratch (device globals, fp16 unless noted). g_Q padded +64 rows.
__device__ __align__(16) __half g_Q[(size_t)(LQ + 64) * DM];   // d 16-blk permuted, pre-scaled QSC
__device__ __align__(16) __half g_V[(size_t)LK * DM];          // plain [token][d]
__device__ __align__(16) __half g_AO[(size_t)LQ * DM];         // k 16-blk permuted
__device__ __align__(16) __half g_xr[(size_t)LK * DM];         // x, k 16-blk permuted
__device__ __align__(16) __half g_Wsr[(size_t)(3 * DM) * DM];  // W_S^T [n][k], permuted
__device__ __align__(16) __half g_Wor[(size_t)DM * DM];        // W_out^T [n][k], permuted
__device__ __align__(16) __half g_Kp[(size_t)LK * DM];         // K, d 16-blk permuted
__device__ __align__(16) __half g_Vt[(size_t)DM * LK];         // V^T [d][token], token permuted
// Split-KV partials: 544 items x [128][64] fp32 O, plus per-row (m, l).
__device__ __align__(16) float g_Po[(size_t)544 * 128 * 64];
__device__ __align__(16) float g_ml[(size_t)544 * 128 * 2];

// 16-block permutation: stored pos 4t..4t+3 hold orig k = 2t, 2t+1, 2t+8, 2t+9.
__device__ __forceinline__ int perm16(int c) {
    return (c < 8) ? (4 * (c >> 1) + (c & 1)) : (4 * ((c - 8) >> 1) + 2 + (c & 1));
}

__device__ __forceinline__ uint32_t h2u(float a, float b) {
    __half2 h = __floats2half2_rn(a, b);
    return *reinterpret_cast<uint32_t*>(&h);
}

__device__ __forceinline__ void mma16(float* c, const uint32_t* a, const uint32_t* b) {
    asm volatile(
        "mma.sync.aligned.m16n8k16.row.col.f32.f16.f16.f32 "
        "{%0,%1,%2,%3}, {%4,%5,%6,%7}, {%8,%9}, {%0,%1,%2,%3};\n"
        : "+f"(c[0]), "+f"(c[1]), "+f"(c[2]), "+f"(c[3])
        : "r"(a[0]), "r"(a[1]), "r"(a[2]), "r"(a[3]), "r"(b[0]), "r"(b[1]));
}

__device__ __forceinline__ void cp16(void* dst, const void* src, int sz) {
    uint32_t d = (uint32_t)__cvta_generic_to_shared(dst);
    asm volatile("cp.async.cg.shared.global [%0], [%1], 16, %2;\n"
                 :: "r"(d), "l"(src), "r"(sz));
}
#define CP_COMMIT()  asm volatile("cp.async.commit_group;\n")
#define CP_WAIT(n)   asm volatile("cp.async.wait_group %0;\n" :: "n"(n))

// ============================================================================
// Prep: x -> fp16 permuted; W_S/W_out -> transpose + fp16 + permuted.
// ============================================================================
__global__ void __launch_bounds__(256)
prep_x(const float* __restrict__ x) {
    const int NB = (int)((size_t)LK * DM / 16);
    for (int i = blockIdx.x * blockDim.x + threadIdx.x; i < NB;
         i += gridDim.x * blockDim.x) {
        const float4* f = (const float4*)(x + (size_t)i * 16);
        float4 f0 = f[0], f1 = f[1], f2 = f[2], f3 = f[3];
        uint4 w0, w1;
        w0.x = h2u(f0.x, f0.y);  w0.y = h2u(f2.x, f2.y);
        w0.z = h2u(f0.z, f0.w);  w0.w = h2u(f2.z, f2.w);
        w1.x = h2u(f1.x, f1.y);  w1.y = h2u(f3.x, f3.y);
        w1.z = h2u(f1.z, f1.w);  w1.w = h2u(f3.z, f3.w);
        *(uint4*)&g_xr[(size_t)i * 16]     = w0;
        *(uint4*)&g_xr[(size_t)i * 16 + 8] = w1;
    }
}

__global__ void __launch_bounds__(256)
prep_tr(const float* __restrict__ src, int which) {
    __shared__ float t[32][33];
    const int C = which ? DM : 3 * DM;
    __half* dst = which ? g_Wor : g_Wsr;
    const int c0 = blockIdx.x * 32, r0 = blockIdx.y * 32;
    const int tx = threadIdx.x & 31, ty = threadIdx.x >> 5;
#pragma unroll
    for (int i = 0; i < 4; i++)
        t[ty + i * 8][tx] = src[(size_t)(r0 + ty + i * 8) * C + c0 + tx];
    __syncthreads();
    const int pk = r0 + (tx & ~15) + perm16(tx & 15);
#pragma unroll
    for (int i = 0; i < 4; i++)
        dst[(size_t)(c0 + ty + i * 8) * DM + pk] = __float2half_rn(t[tx][ty + i * 8]);
}

// V transpose repack: fp16 [d][token], token 16-block permuted.
__global__ void __launch_bounds__(256)
repack_Vt() {
    __shared__ __half t[32][34];
    const int tok0 = blockIdx.x * 32, d0 = blockIdx.y * 32;
    const int tx = threadIdx.x & 31, ty = threadIdx.x >> 5;
#pragma unroll
    for (int i = 0; i < 4; i++)
        t[ty + i * 8][tx] = g_V[(size_t)(tok0 + ty + i * 8) * DM + d0 + tx];
    __syncthreads();
    const int ptok = tok0 + (tx & ~15) + perm16(tx & 15);
#pragma unroll
    for (int i = 0; i < 4; i++)
        g_Vt[(size_t)(d0 + ty + i * 8) * LK + ptok] = t[tx][ty + i * 8];
}

// ============================================================================
// fp16 warp-MMA GEMM tile (m16n8k16): k-chunk 64, 2 stages, 1 barrier/iter.
// (R14 configuration — measured local optimum.)
// ============================================================================
template <int MODE>
__device__ __forceinline__ void gemm_tile(const __half* __restrict__ A,
                                          const __half* __restrict__ Bt,
                                          float* __restrict__ C,
                                          int M, int N, int Ks, int kBeg, int kLen,
                                          int mBase, int nBase, __half* sm) {
    __half* As0 = sm;
    __half* As1 = sm + 9216;
    __half* Bs0 = sm + 18432;
    __half* Bs1 = sm + 27648;

    const int tid  = threadIdx.x;
    const int warp = tid >> 5, lane = tid & 31;
    const int gid  = lane >> 2, tig = lane & 3;
    const int wm = (warp >> 2) * 64;
    const int wn = (warp & 3) * 32;

    float c[4][4][4];
#pragma unroll
    for (int i = 0; i < 4; i++)
#pragma unroll
        for (int j = 0; j < 4; j++)
#pragma unroll
            for (int e = 0; e < 4; e++) c[i][j][e] = 0.f;

    auto issue = [&](int k0, __half* As, __half* Bs) {
#pragma unroll
        for (int i = 0; i < 4; i++) {
            int ch  = tid + i * 256;        // 0..1023
            int row = ch >> 3;
            int cc  = (ch & 7) * 8;
            int grow = mBase + row;
            int ok = (MODE == 1) ? (grow < M) : 1;
            cp16(&As[row * 72 + cc], A + (size_t)(ok ? grow : 0) * Ks + k0 + cc,
                 ok ? 16 : 0);
            cp16(&Bs[row * 72 + cc], Bt + (size_t)(nBase + row) * Ks + k0 + cc, 16);
        }
        CP_COMMIT();
    };

    issue(kBeg, As0, Bs0);

    const int T = kLen / 64;
    for (int t = 0; t < T; t++) {
        CP_WAIT(0);
        __syncthreads();
        if (t + 1 < T)
            issue(kBeg + (t + 1) * 64, (t & 1) ? As0 : As1, (t & 1) ? Bs0 : Bs1);
        __half* As = (t & 1) ? As1 : As0;
        __half* Bs = (t & 1) ? Bs1 : Bs0;

#pragma unroll
        for (int ks = 0; ks < 4; ks++) {
            const int off = ks * 16 + 4 * tig;
            uint32_t a[4][4];
#pragma unroll
            for (int mt = 0; mt < 4; mt++) {
                int r = wm + mt * 16 + gid;
                uint2 u0 = *(const uint2*)&As[r * 72 + off];
                uint2 u1 = *(const uint2*)&As[(r + 8) * 72 + off];
                a[mt][0] = u0.x; a[mt][1] = u1.x; a[mt][2] = u0.y; a[mt][3] = u1.y;
            }
            uint32_t b[4][2];
#pragma unroll
            for (int nt = 0; nt < 4; nt++) {
                int rn = wn + nt * 8 + gid;
                uint2 v = *(const uint2*)&Bs[rn * 72 + off];
                b[nt][0] = v.x; b[nt][1] = v.y;
            }
#pragma unroll
            for (int mt = 0; mt < 4; mt++)
#pragma unroll
                for (int nt = 0; nt < 4; nt++)
                    mma16(c[mt][nt], a[mt], b[nt]);
        }
    }

#pragma unroll
    for (int mt = 0; mt < 4; mt++) {
#pragma unroll
        for (int nt = 0; nt < 4; nt++) {
            int row0 = mBase + wm + mt * 16 + gid;
            int row1 = row0 + 8;
            int col  = nBase + wn + nt * 8 + 2 * tig;
            float v0 = c[mt][nt][0], v1 = c[mt][nt][1];
            float v2 = c[mt][nt][2], v3 = c[mt][nt][3];
            if (MODE == 0) {
                if (col < DM) {
                    int db = col & ~15, p = perm16(col & 15);
                    if (row0 >= QSTART)
                        *(uint32_t*)&g_Q[(size_t)(row0 - QSTART) * DM + db + p] =
                            h2u(v0 * QSC, v1 * QSC);
                    if (row1 >= QSTART)
                        *(uint32_t*)&g_Q[(size_t)(row1 - QSTART) * DM + db + p] =
                            h2u(v2 * QSC, v3 * QSC);
                } else if (col < 2 * DM) {
                    int ck = col - DM;
                    int db = ck & ~15, p = perm16(ck & 15);
                    *(uint32_t*)&g_Kp[(size_t)row0 * DM + db + p] = h2u(v0, v1);
                    *(uint32_t*)&g_Kp[(size_t)row1 * DM + db + p] = h2u(v2, v3);
                } else {
                    int cv = col - 2 * DM;
                    *(uint32_t*)&g_V[(size_t)row0 * DM + cv] = h2u(v0, v1);
                    *(uint32_t*)&g_V[(size_t)row1 * DM + cv] = h2u(v2, v3);
                }
            } else {
                if (row0 < M) *(float2*)&C[(size_t)row0 * N + col] = make_float2(v0, v1);
                if (row1 < M) *(float2*)&C[(size_t)row1 * N + col] = make_float2(v2, v3);
            }
        }
    }
}

// ============================================================================
// Fused qkv: 640 live GEMM tiles + 192 NS streaming blocks (10:3 interleave).
// ============================================================================
extern __shared__ char dynsm[];

__global__ void __launch_bounds__(256, 2)
fused_qkv(const float* __restrict__ x, const float* __restrict__ W_NS) {
    const int bid = blockIdx.x;
    const int grp = bid / 13, rem = bid % 13;
    if (rem < 10) {
        const int g = grp * 10 + rem;       // 0..639
        int mt, nt;
        if (g < 384) { mt = 16 + g / 24; nt = g % 24; }            // rows>=2048: QKV
        else { int g2 = g - 384; mt = g2 / 16; nt = 8 + g2 % 16; } // rows<2048: KV only
        gemm_tile<0>((const __half*)g_xr, (const __half*)g_Wsr, nullptr,
                     4096, 3072, 1024, 0, 1024, mt * 128, nt * 128, (__half*)dynsm);
    } else {
        float* xs = (float*)dynsm;
        const int ns  = grp * 3 + (rem - 10);   // 0..191
        const int tok = ns / 3;
        const int cb  = ns % 3;                 // 0=Q, 1=K, 2=V
        const int c4  = cb * 1024 + threadIdx.x * 4;

        const float* xr = x + (size_t)(L_S_C + tok) * DM;
        for (int i = threadIdx.x; i < DM; i += 256) xs[i] = xr[i];
        __syncthreads();

        const float* Wp = W_NS + (size_t)tok * DM * 3072 + c4;
        float4 acc = make_float4(0.f, 0.f, 0.f, 0.f);
#pragma unroll 8
        for (int d = 0; d < DM; d++) {
            float4 w = __ldcs((const float4*)(Wp + (size_t)d * 3072));
            float xv = xs[d];
            acc.x = fmaf(xv, w.x, acc.x);
            acc.y = fmaf(xv, w.y, acc.y);
            acc.z = fmaf(xv, w.z, acc.z);
            acc.w = fmaf(xv, w.w, acc.w);
        }

        if (cb == 0) {
            int db = c4 & ~15, c16 = c4 & 15;
            __half* qd = g_Q + (size_t)(QSTART + tok) * DM + db;
            *(uint32_t*)&qd[perm16(c16)]     = h2u(acc.x * QSC, acc.y * QSC);
            *(uint32_t*)&qd[perm16(c16 + 2)] = h2u(acc.z * QSC, acc.w * QSC);
        } else if (cb == 1) {
            int ck = c4 - 1024;
            int db = ck & ~15, c16 = ck & 15;
            __half* kd = g_Kp + (size_t)(L_S_C + tok) * DM + db;
            *(uint32_t*)&kd[perm16(c16)]     = h2u(acc.x, acc.y);
            *(uint32_t*)&kd[perm16(c16 + 2)] = h2u(acc.z, acc.w);
        } else {
            uint2 w; w.x = h2u(acc.x, acc.y); w.y = h2u(acc.z, acc.w);
            *(uint2*)&g_V[(size_t)(L_S_C + tok) * DM + (c4 - 2048)] = w;
        }
    }
}

// Output projection: full K, direct stores.
__global__ void __launch_bounds__(256, 2)
gemm_out(float* __restrict__ C) {
    gemm_tile<1>((const __half*)g_AO, (const __half*)g_Wor, C, LQ, 1024, 1024,
                 0, 1024, blockIdx.y * 128, blockIdx.x * 128, (__half*)dynsm);
}

// ============================================================================
// Flash attention v10 (fp16, split-KV x2): 544 CTAs, each = (qtp, head, half).
// Inner loop identical to R14 v8; writes UNNORMALIZED partial (O fp32, m, l).
// bid: qtp = 16 - (bid>>5) [longest first], h = (bid>>1)&15, half = bid&1.
// ============================================================================
__global__ void __launch_bounds__(256, 2)
attn_kernel() {
    __half* KsA = (__half*)dynsm;          // [64][72]
    __half* KsB = (__half*)dynsm + 4608;
    __half* VsA = (__half*)dynsm + 9216;
    __half* VsB = (__half*)dynsm + 13824;

    const int bid = blockIdx.x;
    const int qtp = 16 - (bid >> 5);
    const int h   = (bid >> 1) & 15;
    const int half = bid & 1;
    const int qb  = qtp * 128;
    const int tid  = threadIdx.x;
    const int warp = tid >> 5, lane = tid & 31;
    const int gid  = lane >> 2, tig = lane & 3;
    const int rq0  = warp * 16 + gid;

    const int nktFull = 34 + 2 * qtp;
    const int nkt = nktFull < 65 ? nktFull : 65;
    const int kBeg = half ? nkt / 2 : 0;
    const int kEnd = half ? nkt : nkt / 2;

    auto loadKV = [&](int kt, __half* Kd, __half* Vd) {
        const __half* kp = g_Kp + (size_t)kt * 64 * DM + h * DH;
        const __half* vp = g_Vt + (size_t)h * DH * LK + (size_t)kt * 64;
#pragma unroll
        for (int i = 0; i < 2; i++) {
            int ch = tid + i * 256;        // 0..511
            int r = ch >> 3, cc = (ch & 7) * 8;
            cp16(&Kd[r * 72 + cc], kp + (size_t)r * DM + cc, 16);
            cp16(&Vd[r * 72 + cc], vp + (size_t)r * LK + cc, 16);
        }
        CP_COMMIT();
    };

    loadKV(kBeg, (kBeg & 1) ? KsB : KsA, (kBeg & 1) ? VsB : VsA);

    // Q fragments straight from gmem (pre-scaled, permuted).
    uint32_t qa[4][4];
    {
        const __half* q0 = g_Q + (size_t)(qb + rq0) * DM + h * DH;
        const __half* q1 = g_Q + (size_t)(qb + rq0 + 8) * DM + h * DH;
#pragma unroll
        for (int ks = 0; ks < 4; ks++) {
            uint2 u0 = *(const uint2*)(q0 + ks * 16 + 4 * tig);
            uint2 u1 = *(const uint2*)(q1 + ks * 16 + 4 * tig);
            qa[ks][0] = u0.x; qa[ks][1] = u1.x; qa[ks][2] = u0.y; qa[ks][3] = u1.y;
        }
    }

    float m0 = -1e30f, m1 = -1e30f;
    float sc0s = 0.f, sc1s = 0.f;
    uint32_t pa[4][4];
    const uint32_t oneb[2] = {0x3C003C00u, 0x3C003C00u};
    float ol[4] = {0.f, 0.f, 0.f, 0.f};
    float o[8][4];
#pragma unroll
    for (int i = 0; i < 8; i++)
#pragma unroll
        for (int e = 0; e < 4; e++) o[i][e] = 0.f;

    for (int kt = kBeg; kt < kEnd; kt++) {
        CP_WAIT(0);
        __syncthreads();

        __half* Ks = (kt & 1) ? KsB : KsA;

        // ---- S(kt) = Q @ K^T ----
        float s[8][4];
#pragma unroll
        for (int i = 0; i < 8; i++)
#pragma unroll
            for (int e = 0; e < 4; e++) s[i][e] = 0.f;

#pragma unroll
        for (int ks = 0; ks < 4; ks++) {
            const int off = ks * 16 + 4 * tig;
#pragma unroll
            for (int nt = 0; nt < 8; nt++) {
                uint2 kv = *(const uint2*)&Ks[(nt * 8 + gid) * 72 + off];
                uint32_t bb[2] = {kv.x, kv.y};
                mma16(s[nt], qa[ks], bb);
            }
        }

        // ---- deferred PV(kt-1) ----
        if (kt > kBeg) {
            __half* Vp = (kt & 1) ? VsA : VsB;
#pragma unroll
            for (int dt = 0; dt < 8; dt++) {
                o[dt][0] *= sc0s; o[dt][1] *= sc0s;
                o[dt][2] *= sc1s; o[dt][3] *= sc1s;
            }
            ol[0] *= sc0s; ol[1] *= sc0s; ol[2] *= sc1s; ol[3] *= sc1s;
#pragma unroll
            for (int g = 0; g < 4; g++) {
                const int off = g * 16 + 4 * tig;
#pragma unroll
                for (int dt = 0; dt < 8; dt++) {
                    uint2 vv = *(const uint2*)&Vp[(dt * 8 + gid) * 72 + off];
                    uint32_t bb[2] = {vv.x, vv.y};
                    mma16(o[dt], pa[g], bb);
                }
                mma16(ol, pa[g], oneb);
            }
        }

        __syncthreads();
        if (kt + 1 < kEnd)
            loadKV(kt + 1, (kt & 1) ? KsA : KsB, (kt & 1) ? VsA : VsB);

        // ---- causal mask on last two k-tiles of the FULL range ----
        if (kt >= nkt - 2) {
            const int off = kt * 64 - QSTART - qb;
#pragma unroll
            for (int nt = 0; nt < 8; nt++) {
#pragma unroll
                for (int e = 0; e < 4; e++) {
                    int kc  = nt * 8 + 2 * tig + (e & 1);
                    int rit = warp * 16 + gid + ((e >> 1) << 3);
                    if (kc + off > rit) s[nt][e] = -1e30f;
                }
            }
        }

        // ---- online softmax(kt) ----
        float rm0 = -1e30f, rm1 = -1e30f;
#pragma unroll
        for (int nt = 0; nt < 8; nt++) {
            rm0 = fmaxf(rm0, fmaxf(s[nt][0], s[nt][1]));
            rm1 = fmaxf(rm1, fmaxf(s[nt][2], s[nt][3]));
        }
        rm0 = fmaxf(rm0, __shfl_xor_sync(0xffffffffu, rm0, 1));
        rm0 = fmaxf(rm0, __shfl_xor_sync(0xffffffffu, rm0, 2));
        rm1 = fmaxf(rm1, __shfl_xor_sync(0xffffffffu, rm1, 1));
        rm1 = fmaxf(rm1, __shfl_xor_sync(0xffffffffu, rm1, 2));

        float mn0 = fmaxf(m0, rm0), mn1 = fmaxf(m1, rm1);
        sc0s = exp2f(m0 - mn0);
        sc1s = exp2f(m1 - mn1);
        m0 = mn0; m1 = mn1;

        // ---- pack P(kt) into register A-fragments ----
#pragma unroll
        for (int g = 0; g < 4; g++) {
            pa[g][0] = h2u(exp2f(s[2 * g][0] - m0),     exp2f(s[2 * g][1] - m0));
            pa[g][1] = h2u(exp2f(s[2 * g][2] - m1),     exp2f(s[2 * g][3] - m1));
            pa[g][2] = h2u(exp2f(s[2 * g + 1][0] - m0), exp2f(s[2 * g + 1][1] - m0));
            pa[g][3] = h2u(exp2f(s[2 * g + 1][2] - m1), exp2f(s[2 * g + 1][3] - m1));
        }
    }

    // ---- final deferred PV(kEnd-1) ----
    {
        __half* Vp = ((kEnd - 1) & 1) ? VsB : VsA;
#pragma unroll
        for (int dt = 0; dt < 8; dt++) {
            o[dt][0] *= sc0s; o[dt][1] *= sc0s;
            o[dt][2] *= sc1s; o[dt][3] *= sc1s;
        }
        ol[0] *= sc0s; ol[1] *= sc0s; ol[2] *= sc1s; ol[3] *= sc1s;
#pragma unroll
        for (int g = 0; g < 4; g++) {
            const int off = g * 16 + 4 * tig;
#pragma unroll
            for (int dt = 0; dt < 8; dt++) {
                uint2 vv = *(const uint2*)&Vp[(dt * 8 + gid) * 72 + off];
                uint32_t bb[2] = {vv.x, vv.y};
                mma16(o[dt], pa[g], bb);
            }
            mma16(ol, pa[g], oneb);
        }
    }

    // ---- write unnormalized partial ----
    float* po = g_Po + (size_t)bid * 8192;
#pragma unroll
    for (int dt = 0; dt < 8; dt++) {
        int col = dt * 8 + 2 * tig;
        *(float2*)&po[rq0 * 64 + col]       = make_float2(o[dt][0], o[dt][1]);
        *(float2*)&po[(rq0 + 8) * 64 + col] = make_float2(o[dt][2], o[dt][3]);
    }
    if (tig == 0) {
        float* ml = g_ml + (size_t)bid * 256;
        ml[rq0 * 2]           = m0;
        ml[rq0 * 2 + 1]       = ol[0];
        ml[(rq0 + 8) * 2]     = m1;
        ml[(rq0 + 8) * 2 + 1] = ol[2];
    }
}

// ============================================================================
// Combine the two split-KV partials per (qtp, head) tile -> g_AO fp16 permuted.
// grid 272; cid: idx = cid>>4 (qtp = 16-idx), h = cid&15.
// ============================================================================
__global__ void __launch_bounds__(256)
combine_attn() {
    const int cid = blockIdx.x;
    const int idx = cid >> 4, h = cid & 15;
    const int qtp = 16 - idx;
    const int qb  = qtp * 128;
    const int pid0 = idx * 32 + h * 2;
    const int pid1 = pid0 + 1;

    const int t = threadIdx.x;
    const int r = t >> 1;
    const int cbase = (t & 1) * 32;
    if (qb + r >= LQ) return;

    const float* ml0 = g_ml + (size_t)pid0 * 256 + r * 2;
    const float* ml1 = g_ml + (size_t)pid1 * 256 + r * 2;
    float ma = ml0[0], la = ml0[1];
    float mb = ml1[0], lb = ml1[1];
    float m = fmaxf(ma, mb);
    float wa = exp2f(ma - m), wb = exp2f(mb - m);
    float inv = 1.f / (la * wa + lb * wb);
    wa *= inv; wb *= inv;

    const float* oa = g_Po + (size_t)pid0 * 8192 + r * 64;
    const float* ob = g_Po + (size_t)pid1 * 8192 + r * 64;
    __half* dst = g_AO + (size_t)(qb + r) * DM + h * DH;
#pragma unroll
    for (int c = 0; c < 32; c += 2) {
        int cc = cbase + c;
        float2 va = *(const float2*)&oa[cc];
        float2 vb = *(const float2*)&ob[cc];
        float u0 = va.x * wa + vb.x * wb;
        float u1 = va.y * wa + vb.y * wb;
        *(uint32_t*)&dst[(cc & ~15) + perm16(cc & 15)] = h2u(u0, u1);
    }
}

// ============================================================================
extern "C" void kernel_launch(void* const* d_in, const int* in_sizes, int n_in,
                              void* d_out, int out_size) {
    const float* x     = (const float*)d_in[0];
    const float* W_S   = (const float*)d_in[1];
    const float* W_NS  = (const float*)d_in[2];
    const float* W_out = (const float*)d_in[3];
    float* out = (float*)d_out;
    (void)in_sizes; (void)n_in; (void)out_size;

    const int gemm_smem = 36864 * 2;   // 73728 B
    const int attn_smem = 18432 * 2;   // 36864 B

    cudaFuncSetAttribute(fused_qkv,   cudaFuncAttributeMaxDynamicSharedMemorySize, gemm_smem);
    cudaFuncSetAttribute(gemm_out,    cudaFuncAttributeMaxDynamicSharedMemorySize, gemm_smem);
    cudaFuncSetAttribute(attn_kernel, cudaFuncAttributeMaxDynamicSharedMemorySize, attn_smem);

    // 0) prep: x/W_S/W_out -> fp16 permuted
    prep_x<<<512, 256>>>(x);
    prep_tr<<<dim3(3 * DM / 32, DM / 32), 256>>>(W_S, 0);
    prep_tr<<<dim3(DM / 32, DM / 32), 256>>>(W_out, 1);

    // 1+2) fused: live qkv GEMM tiles (640) + NS streaming (192)
    fused_qkv<<<832, 256, gemm_smem>>>(x, W_NS);

    // 2b) repack V (transpose + token 16-blk permute)
    repack_Vt<<<dim3(LK / 32, DM / 32), 256>>>();

    // 3) attention, split-KV x2: 544 half-range CTAs, longest first
    attn_kernel<<<544, 256, attn_smem>>>();
    combine_attn<<<272, 256>>>();

    // 4) output projection, full K, direct stores
    gemm_out<<<dim3(1024 / 128, (LQ + 127) / 128), 256, gemm_smem>>>(out);
}

// round 17
// speedup vs baseline: 1.2763x; 1.0921x over previous
#include <cuda_runtime.h>
#include <cuda_fp16.h>
#include <cstdint>
#include <cstddef>

// Problem constants
#define L_S_C   4096
#define QSTART  2048
#define L_NS_C  64
#define LQ      2112
#define LK      4160
#define DM      1024
#define NH      16
#define DH      64

// Q pre-scale: Dh^-0.5 * log2(e)  (softmax runs in exp2 domain)
#define QSC     0.18033688011f

// Scratch (device globals, fp16 unless noted). g_Q padded +64 rows.
__device__ __align__(16) __half g_Q[(size_t)(LQ + 64) * DM];   // d 16-blk permuted, pre-scaled QSC
__device__ __align__(16) __half g_V[(size_t)LK * DM];          // plain [token][d]
__device__ __align__(16) __half g_AO[(size_t)LQ * DM];         // k 16-blk permuted
__device__ __align__(16) __half g_xr[(size_t)LK * DM];         // x, k 16-blk permuted
__device__ __align__(16) __half g_Wsr[(size_t)(3 * DM) * DM];  // W_S^T [n][k], permuted
__device__ __align__(16) __half g_Wor[(size_t)DM * DM];        // W_out^T [n][k], permuted
__device__ __align__(16) __half g_Kp[(size_t)LK * DM];         // K, d 16-blk permuted
__device__ __align__(16) __half g_Vt[(size_t)DM * LK];         // V^T [d][token], token permuted
// Split-KV partials: 544 items x [128][64] fp32 O, plus per-row (m, l).
__device__ __align__(16) float g_Po[(size_t)544 * 128 * 64];
__device__ __align__(16) float g_ml[(size_t)544 * 128 * 2];
// NS GEMV k-quarter partials: [kq][tok][3072] fp32.
__device__ __align__(16) float g_NSp[(size_t)4 * L_NS_C * 3072];

// 16-block permutation: stored pos 4t..4t+3 hold orig k = 2t, 2t+1, 2t+8, 2t+9.
__device__ __forceinline__ int perm16(int c) {
    return (c < 8) ? (4 * (c >> 1) + (c & 1)) : (4 * ((c - 8) >> 1) + 2 + (c & 1));
}

__device__ __forceinline__ uint32_t h2u(float a, float b) {
    __half2 h = __floats2half2_rn(a, b);
    return *reinterpret_cast<uint32_t*>(&h);
}

__device__ __forceinline__ void mma16(float* c, const uint32_t* a, const uint32_t* b) {
    asm volatile(
        "mma.sync.aligned.m16n8k16.row.col.f32.f16.f16.f32 "
        "{%0,%1,%2,%3}, {%4,%5,%6,%7}, {%8,%9}, {%0,%1,%2,%3};\n"
        : "+f"(c[0]), "+f"(c[1]), "+f"(c[2]), "+f"(c[3])
        : "r"(a[0]), "r"(a[1]), "r"(a[2]), "r"(a[3]), "r"(b[0]), "r"(b[1]));
}

__device__ __forceinline__ void cp16(void* dst, const void* src, int sz) {
    uint32_t d = (uint32_t)__cvta_generic_to_shared(dst);
    asm volatile("cp.async.cg.shared.global [%0], [%1], 16, %2;\n"
                 :: "r"(d), "l"(src), "r"(sz));
}
#define CP_COMMIT()  asm volatile("cp.async.commit_group;\n")
#define CP_WAIT(n)   asm volatile("cp.async.wait_group %0;\n" :: "n"(n))

// ============================================================================
// Prep: x -> fp16 permuted; W_S/W_out -> transpose + fp16 + permuted.
// ============================================================================
__global__ void __launch_bounds__(256)
prep_x(const float* __restrict__ x) {
    const int NB = (int)((size_t)LK * DM / 16);
    for (int i = blockIdx.x * blockDim.x + threadIdx.x; i < NB;
         i += gridDim.x * blockDim.x) {
        const float4* f = (const float4*)(x + (size_t)i * 16);
        float4 f0 = f[0], f1 = f[1], f2 = f[2], f3 = f[3];
        uint4 w0, w1;
        w0.x = h2u(f0.x, f0.y);  w0.y = h2u(f2.x, f2.y);
        w0.z = h2u(f0.z, f0.w);  w0.w = h2u(f2.z, f2.w);
        w1.x = h2u(f1.x, f1.y);  w1.y = h2u(f3.x, f3.y);
        w1.z = h2u(f1.z, f1.w);  w1.w = h2u(f3.z, f3.w);
        *(uint4*)&g_xr[(size_t)i * 16]     = w0;
        *(uint4*)&g_xr[(size_t)i * 16 + 8] = w1;
    }
}

__global__ void __launch_bounds__(256)
prep_tr(const float* __restrict__ src, int which) {
    __shared__ float t[32][33];
    const int C = which ? DM : 3 * DM;
    __half* dst = which ? g_Wor : g_Wsr;
    const int c0 = blockIdx.x * 32, r0 = blockIdx.y * 32;
    const int tx = threadIdx.x & 31, ty = threadIdx.x >> 5;
#pragma unroll
    for (int i = 0; i < 4; i++)
        t[ty + i * 8][tx] = src[(size_t)(r0 + ty + i * 8) * C + c0 + tx];
    __syncthreads();
    const int pk = r0 + (tx & ~15) + perm16(tx & 15);
#pragma unroll
    for (int i = 0; i < 4; i++)
        dst[(size_t)(c0 + ty + i * 8) * DM + pk] = __float2half_rn(t[tx][ty + i * 8]);
}

// V transpose repack: fp16 [d][token], token 16-block permuted.
__global__ void __launch_bounds__(256)
repack_Vt() {
    __shared__ __half t[32][34];
    const int tok0 = blockIdx.x * 32, d0 = blockIdx.y * 32;
    const int tx = threadIdx.x & 31, ty = threadIdx.x >> 5;
#pragma unroll
    for (int i = 0; i < 4; i++)
        t[ty + i * 8][tx] = g_V[(size_t)(tok0 + ty + i * 8) * DM + d0 + tx];
    __syncthreads();
    const int ptok = tok0 + (tx & ~15) + perm16(tx & 15);
#pragma unroll
    for (int i = 0; i < 4; i++)
        g_Vt[(size_t)(d0 + ty + i * 8) * LK + ptok] = t[tx][ty + i * 8];
}

// ============================================================================
// fp16 warp-MMA GEMM tile (m16n8k16): k-chunk 64, 2 stages, 1 barrier/iter.
// ============================================================================
template <int MODE>
__device__ __forceinline__ void gemm_tile(const __half* __restrict__ A,
                                          const __half* __restrict__ Bt,
                                          float* __restrict__ C,
                                          int M, int N, int Ks, int kBeg, int kLen,
                                          int mBase, int nBase, __half* sm) {
    __half* As0 = sm;
    __half* As1 = sm + 9216;
    __half* Bs0 = sm + 18432;
    __half* Bs1 = sm + 27648;

    const int tid  = threadIdx.x;
    const int warp = tid >> 5, lane = tid & 31;
    const int gid  = lane >> 2, tig = lane & 3;
    const int wm = (warp >> 2) * 64;
    const int wn = (warp & 3) * 32;

    float c[4][4][4];
#pragma unroll
    for (int i = 0; i < 4; i++)
#pragma unroll
        for (int j = 0; j < 4; j++)
#pragma unroll
            for (int e = 0; e < 4; e++) c[i][j][e] = 0.f;

    auto issue = [&](int k0, __half* As, __half* Bs) {
#pragma unroll
        for (int i = 0; i < 4; i++) {
            int ch  = tid + i * 256;        // 0..1023
            int row = ch >> 3;
            int cc  = (ch & 7) * 8;
            int grow = mBase + row;
            int ok = (MODE == 1) ? (grow < M) : 1;
            cp16(&As[row * 72 + cc], A + (size_t)(ok ? grow : 0) * Ks + k0 + cc,
                 ok ? 16 : 0);
            cp16(&Bs[row * 72 + cc], Bt + (size_t)(nBase + row) * Ks + k0 + cc, 16);
        }
        CP_COMMIT();
    };

    issue(kBeg, As0, Bs0);

    const int T = kLen / 64;
    for (int t = 0; t < T; t++) {
        CP_WAIT(0);
        __syncthreads();
        if (t + 1 < T)
            issue(kBeg + (t + 1) * 64, (t & 1) ? As0 : As1, (t & 1) ? Bs0 : Bs1);
        __half* As = (t & 1) ? As1 : As0;
        __half* Bs = (t & 1) ? Bs1 : Bs0;

#pragma unroll
        for (int ks = 0; ks < 4; ks++) {
            const int off = ks * 16 + 4 * tig;
            uint32_t a[4][4];
#pragma unroll
            for (int mt = 0; mt < 4; mt++) {
                int r = wm + mt * 16 + gid;
                uint2 u0 = *(const uint2*)&As[r * 72 + off];
                uint2 u1 = *(const uint2*)&As[(r + 8) * 72 + off];
                a[mt][0] = u0.x; a[mt][1] = u1.x; a[mt][2] = u0.y; a[mt][3] = u1.y;
            }
            uint32_t b[4][2];
#pragma unroll
            for (int nt = 0; nt < 4; nt++) {
                int rn = wn + nt * 8 + gid;
                uint2 v = *(const uint2*)&Bs[rn * 72 + off];
                b[nt][0] = v.x; b[nt][1] = v.y;
            }
#pragma unroll
            for (int mt = 0; mt < 4; mt++)
#pragma unroll
                for (int nt = 0; nt < 4; nt++)
                    mma16(c[mt][nt], a[mt], b[nt]);
        }
    }

#pragma unroll
    for (int mt = 0; mt < 4; mt++) {
#pragma unroll
        for (int nt = 0; nt < 4; nt++) {
            int row0 = mBase + wm + mt * 16 + gid;
            int row1 = row0 + 8;
            int col  = nBase + wn + nt * 8 + 2 * tig;
            float v0 = c[mt][nt][0], v1 = c[mt][nt][1];
            float v2 = c[mt][nt][2], v3 = c[mt][nt][3];
            if (MODE == 0) {
                if (col < DM) {
                    int db = col & ~15, p = perm16(col & 15);
                    if (row0 >= QSTART)
                        *(uint32_t*)&g_Q[(size_t)(row0 - QSTART) * DM + db + p] =
                            h2u(v0 * QSC, v1 * QSC);
                    if (row1 >= QSTART)
                        *(uint32_t*)&g_Q[(size_t)(row1 - QSTART) * DM + db + p] =
                            h2u(v2 * QSC, v3 * QSC);
                } else if (col < 2 * DM) {
                    int ck = col - DM;
                    int db = ck & ~15, p = perm16(ck & 15);
                    *(uint32_t*)&g_Kp[(size_t)row0 * DM + db + p] = h2u(v0, v1);
                    *(uint32_t*)&g_Kp[(size_t)row1 * DM + db + p] = h2u(v2, v3);
                } else {
                    int cv = col - 2 * DM;
                    *(uint32_t*)&g_V[(size_t)row0 * DM + cv] = h2u(v0, v1);
                    *(uint32_t*)&g_V[(size_t)row1 * DM + cv] = h2u(v2, v3);
                }
            } else {
                if (row0 < M) *(float2*)&C[(size_t)row0 * N + col] = make_float2(v0, v1);
                if (row1 < M) *(float2*)&C[(size_t)row1 * N + col] = make_float2(v2, v3);
            }
        }
    }
}

// ============================================================================
// Fused qkv: 640 GEMM tiles + 768 NS k-quarter GEMV blocks (5:6 per 11 bids).
// NS block (tok, cb, kq): 256 d-iters over 1024 cols -> fp32 partial g_NSp.
// ============================================================================
extern __shared__ char dynsm[];

__global__ void __launch_bounds__(256, 2)
fused_qkv(const float* __restrict__ x, const float* __restrict__ W_NS) {
    const int bid = blockIdx.x;
    const int grp = bid / 11, rem = bid % 11;
    if (rem < 5) {
        const int g = grp * 5 + rem;        // 0..639
        int mt, nt;
        if (g < 384) { mt = 16 + g / 24; nt = g % 24; }            // rows>=2048: QKV
        else { int g2 = g - 384; mt = g2 / 16; nt = 8 + g2 % 16; } // rows<2048: KV only
        gemm_tile<0>((const __half*)g_xr, (const __half*)g_Wsr, nullptr,
                     4096, 3072, 1024, 0, 1024, mt * 128, nt * 128, (__half*)dynsm);
    } else {
        float* xs = (float*)dynsm;
        const int ns  = grp * 6 + (rem - 5);    // 0..767
        const int tok = ns / 12;
        const int cb  = (ns >> 2) % 3;          // 0=Q, 1=K, 2=V
        const int kq  = ns & 3;                 // k quarter
        const int c4  = cb * 1024 + threadIdx.x * 4;
        const int d0  = kq * 256;

        xs[threadIdx.x] = x[(size_t)(L_S_C + tok) * DM + d0 + threadIdx.x];
        __syncthreads();

        const float* Wp = W_NS + (size_t)tok * DM * 3072 + (size_t)d0 * 3072 + c4;
        float4 acc = make_float4(0.f, 0.f, 0.f, 0.f);
#pragma unroll 8
        for (int d = 0; d < 256; d++) {
            float4 w = __ldcs((const float4*)(Wp + (size_t)d * 3072));
            float xv = xs[d];
            acc.x = fmaf(xv, w.x, acc.x);
            acc.y = fmaf(xv, w.y, acc.y);
            acc.z = fmaf(xv, w.z, acc.z);
            acc.w = fmaf(xv, w.w, acc.w);
        }
        *(float4*)&g_NSp[((size_t)kq * L_NS_C + tok) * 3072 + c4] = acc;
    }
}

// Sum the 4 k-quarter partials, convert + permute + scatter (as before).
__global__ void __launch_bounds__(256)
ns_finalize() {
    const int i   = blockIdx.x * 256 + threadIdx.x;   // 0..49151
    const int tok = i / 768;
    const int c4  = (i % 768) * 4;                    // 0..3068
    const size_t base = (size_t)tok * 3072 + c4;
    float4 p0 = *(const float4*)&g_NSp[base];
    float4 p1 = *(const float4*)&g_NSp[(size_t)L_NS_C * 3072 + base];
    float4 p2 = *(const float4*)&g_NSp[(size_t)2 * L_NS_C * 3072 + base];
    float4 p3 = *(const float4*)&g_NSp[(size_t)3 * L_NS_C * 3072 + base];
    float4 acc;
    acc.x = (p0.x + p1.x) + (p2.x + p3.x);
    acc.y = (p0.y + p1.y) + (p2.y + p3.y);
    acc.z = (p0.z + p1.z) + (p2.z + p3.z);
    acc.w = (p0.w + p1.w) + (p2.w + p3.w);

    const int cb = c4 >> 10;
    if (cb == 0) {
        int db = c4 & ~15, c16 = c4 & 15;
        __half* qd = g_Q + (size_t)(QSTART + tok) * DM + db;
        *(uint32_t*)&qd[perm16(c16)]     = h2u(acc.x * QSC, acc.y * QSC);
        *(uint32_t*)&qd[perm16(c16 + 2)] = h2u(acc.z * QSC, acc.w * QSC);
    } else if (cb == 1) {
        int ck = c4 - 1024;
        int db = ck & ~15, c16 = ck & 15;
        __half* kd = g_Kp + (size_t)(L_S_C + tok) * DM + db;
        *(uint32_t*)&kd[perm16(c16)]     = h2u(acc.x, acc.y);
        *(uint32_t*)&kd[perm16(c16 + 2)] = h2u(acc.z, acc.w);
    } else {
        uint2 w; w.x = h2u(acc.x, acc.y); w.y = h2u(acc.z, acc.w);
        *(uint2*)&g_V[(size_t)(L_S_C + tok) * DM + (c4 - 2048)] = w;
    }
}

// Output projection: full K, direct stores.
__global__ void __launch_bounds__(256, 2)
gemm_out(float* __restrict__ C) {
    gemm_tile<1>((const __half*)g_AO, (const __half*)g_Wor, C, LQ, 1024, 1024,
                 0, 1024, blockIdx.y * 128, blockIdx.x * 128, (__half*)dynsm);
}

// ============================================================================
// Flash attention v10 (fp16, split-KV x2): 544 CTAs, each = (qtp, head, half).
// ============================================================================
__global__ void __launch_bounds__(256, 2)
attn_kernel() {
    __half* KsA = (__half*)dynsm;          // [64][72]
    __half* KsB = (__half*)dynsm + 4608;
    __half* VsA = (__half*)dynsm + 9216;
    __half* VsB = (__half*)dynsm + 13824;

    const int bid = blockIdx.x;
    const int qtp = 16 - (bid >> 5);
    const int h   = (bid >> 1) & 15;
    const int half = bid & 1;
    const int qb  = qtp * 128;
    const int tid  = threadIdx.x;
    const int warp = tid >> 5, lane = tid & 31;
    const int gid  = lane >> 2, tig = lane & 3;
    const int rq0  = warp * 16 + gid;

    const int nktFull = 34 + 2 * qtp;
    const int nkt = nktFull < 65 ? nktFull : 65;
    const int kBeg = half ? nkt / 2 : 0;
    const int kEnd = half ? nkt : nkt / 2;

    auto loadKV = [&](int kt, __half* Kd, __half* Vd) {
        const __half* kp = g_Kp + (size_t)kt * 64 * DM + h * DH;
        const __half* vp = g_Vt + (size_t)h * DH * LK + (size_t)kt * 64;
#pragma unroll
        for (int i = 0; i < 2; i++) {
            int ch = tid + i * 256;        // 0..511
            int r = ch >> 3, cc = (ch & 7) * 8;
            cp16(&Kd[r * 72 + cc], kp + (size_t)r * DM + cc, 16);
            cp16(&Vd[r * 72 + cc], vp + (size_t)r * LK + cc, 16);
        }
        CP_COMMIT();
    };

    loadKV(kBeg, (kBeg & 1) ? KsB : KsA, (kBeg & 1) ? VsB : VsA);

    uint32_t qa[4][4];
    {
        const __half* q0 = g_Q + (size_t)(qb + rq0) * DM + h * DH;
        const __half* q1 = g_Q + (size_t)(qb + rq0 + 8) * DM + h * DH;
#pragma unroll
        for (int ks = 0; ks < 4; ks++) {
            uint2 u0 = *(const uint2*)(q0 + ks * 16 + 4 * tig);
            uint2 u1 = *(const uint2*)(q1 + ks * 16 + 4 * tig);
            qa[ks][0] = u0.x; qa[ks][1] = u1.x; qa[ks][2] = u0.y; qa[ks][3] = u1.y;
        }
    }

    float m0 = -1e30f, m1 = -1e30f;
    float sc0s = 0.f, sc1s = 0.f;
    uint32_t pa[4][4];
    const uint32_t oneb[2] = {0x3C003C00u, 0x3C003C00u};
    float ol[4] = {0.f, 0.f, 0.f, 0.f};
    float o[8][4];
#pragma unroll
    for (int i = 0; i < 8; i++)
#pragma unroll
        for (int e = 0; e < 4; e++) o[i][e] = 0.f;

    for (int kt = kBeg; kt < kEnd; kt++) {
        CP_WAIT(0);
        __syncthreads();

        __half* Ks = (kt & 1) ? KsB : KsA;

        float s[8][4];
#pragma unroll
        for (int i = 0; i < 8; i++)
#pragma unroll
            for (int e = 0; e < 4; e++) s[i][e] = 0.f;

#pragma unroll
        for (int ks = 0; ks < 4; ks++) {
            const int off = ks * 16 + 4 * tig;
#pragma unroll
            for (int nt = 0; nt < 8; nt++) {
                uint2 kv = *(const uint2*)&Ks[(nt * 8 + gid) * 72 + off];
                uint32_t bb[2] = {kv.x, kv.y};
                mma16(s[nt], qa[ks], bb);
            }
        }

        if (kt > kBeg) {
            __half* Vp = (kt & 1) ? VsA : VsB;
#pragma unroll
            for (int dt = 0; dt < 8; dt++) {
                o[dt][0] *= sc0s; o[dt][1] *= sc0s;
                o[dt][2] *= sc1s; o[dt][3] *= sc1s;
            }
            ol[0] *= sc0s; ol[1] *= sc0s; ol[2] *= sc1s; ol[3] *= sc1s;
#pragma unroll
            for (int g = 0; g < 4; g++) {
                const int off = g * 16 + 4 * tig;
#pragma unroll
                for (int dt = 0; dt < 8; dt++) {
                    uint2 vv = *(const uint2*)&Vp[(dt * 8 + gid) * 72 + off];
                    uint32_t bb[2] = {vv.x, vv.y};
                    mma16(o[dt], pa[g], bb);
                }
                mma16(ol, pa[g], oneb);
            }
        }

        __syncthreads();
        if (kt + 1 < kEnd)
            loadKV(kt + 1, (kt & 1) ? KsA : KsB, (kt & 1) ? VsA : VsB);

        if (kt >= nkt - 2) {
            const int off = kt * 64 - QSTART - qb;
#pragma unroll
            for (int nt = 0; nt < 8; nt++) {
#pragma unroll
                for (int e = 0; e < 4; e++) {
                    int kc  = nt * 8 + 2 * tig + (e & 1);
                    int rit = warp * 16 + gid + ((e >> 1) << 3);
                    if (kc + off > rit) s[nt][e] = -1e30f;
                }
            }
        }

        float rm0 = -1e30f, rm1 = -1e30f;
#pragma unroll
        for (int nt = 0; nt < 8; nt++) {
            rm0 = fmaxf(rm0, fmaxf(s[nt][0], s[nt][1]));
            rm1 = fmaxf(rm1, fmaxf(s[nt][2], s[nt][3]));
        }
        rm0 = fmaxf(rm0, __shfl_xor_sync(0xffffffffu, rm0, 1));
        rm0 = fmaxf(rm0, __shfl_xor_sync(0xffffffffu, rm0, 2));
        rm1 = fmaxf(rm1, __shfl_xor_sync(0xffffffffu, rm1, 1));
        rm1 = fmaxf(rm1, __shfl_xor_sync(0xffffffffu, rm1, 2));

        float mn0 = fmaxf(m0, rm0), mn1 = fmaxf(m1, rm1);
        sc0s = exp2f(m0 - mn0);
        sc1s = exp2f(m1 - mn1);
        m0 = mn0; m1 = mn1;

#pragma unroll
        for (int g = 0; g < 4; g++) {
            pa[g][0] = h2u(exp2f(s[2 * g][0] - m0),     exp2f(s[2 * g][1] - m0));
            pa[g][1] = h2u(exp2f(s[2 * g][2] - m1),     exp2f(s[2 * g][3] - m1));
            pa[g][2] = h2u(exp2f(s[2 * g + 1][0] - m0), exp2f(s[2 * g + 1][1] - m0));
            pa[g][3] = h2u(exp2f(s[2 * g + 1][2] - m1), exp2f(s[2 * g + 1][3] - m1));
        }
    }

    {
        __half* Vp = ((kEnd - 1) & 1) ? VsB : VsA;
#pragma unroll
        for (int dt = 0; dt < 8; dt++) {
            o[dt][0] *= sc0s; o[dt][1] *= sc0s;
            o[dt][2] *= sc1s; o[dt][3] *= sc1s;
        }
        ol[0] *= sc0s; ol[1] *= sc0s; ol[2] *= sc1s; ol[3] *= sc1s;
#pragma unroll
        for (int g = 0; g < 4; g++) {
            const int off = g * 16 + 4 * tig;
#pragma unroll
            for (int dt = 0; dt < 8; dt++) {
                uint2 vv = *(const uint2*)&Vp[(dt * 8 + gid) * 72 + off];
                uint32_t bb[2] = {vv.x, vv.y};
                mma16(o[dt], pa[g], bb);
            }
            mma16(ol, pa[g], oneb);
        }
    }

    float* po = g_Po + (size_t)bid * 8192;
#pragma unroll
    for (int dt = 0; dt < 8; dt++) {
        int col = dt * 8 + 2 * tig;
        *(float2*)&po[rq0 * 64 + col]       = make_float2(o[dt][0], o[dt][1]);
        *(float2*)&po[(rq0 + 8) * 64 + col] = make_float2(o[dt][2], o[dt][3]);
    }
    if (tig == 0) {
        float* ml = g_ml + (size_t)bid * 256;
        ml[rq0 * 2]           = m0;
        ml[rq0 * 2 + 1]       = ol[0];
        ml[(rq0 + 8) * 2]     = m1;
        ml[(rq0 + 8) * 2 + 1] = ol[2];
    }
}

// ============================================================================
// Combine the two split-KV partials per (qtp, head) tile -> g_AO fp16 permuted.
// ============================================================================
__global__ void __launch_bounds__(256)
combine_attn() {
    const int cid = blockIdx.x;
    const int idx = cid >> 4, h = cid & 15;
    const int qtp = 16 - idx;
    const int qb  = qtp * 128;
    const int pid0 = idx * 32 + h * 2;
    const int pid1 = pid0 + 1;

    const int t = threadIdx.x;
    const int r = t >> 1;
    const int cbase = (t & 1) * 32;
    if (qb + r >= LQ) return;

    const float* ml0 = g_ml + (size_t)pid0 * 256 + r * 2;
    const float* ml1 = g_ml + (size_t)pid1 * 256 + r * 2;
    float ma = ml0[0], la = ml0[1];
    float mb = ml1[0], lb = ml1[1];
    float m = fmaxf(ma, mb);
    float wa = exp2f(ma - m), wb = exp2f(mb - m);
    float inv = 1.f / (la * wa + lb * wb);
    wa *= inv; wb *= inv;

    const float* oa = g_Po + (size_t)pid0 * 8192 + r * 64;
    const float* ob = g_Po + (size_t)pid1 * 8192 + r * 64;
    __half* dst = g_AO + (size_t)(qb + r) * DM + h * DH;
#pragma unroll
    for (int c = 0; c < 32; c += 2) {
        int cc = cbase + c;
        float2 va = *(const float2*)&oa[cc];
        float2 vb = *(const float2*)&ob[cc];
        float u0 = va.x * wa + vb.x * wb;
        float u1 = va.y * wa + vb.y * wb;
        *(uint32_t*)&dst[(cc & ~15) + perm16(cc & 15)] = h2u(u0, u1);
    }
}

// ============================================================================
extern "C" void kernel_launch(void* const* d_in, const int* in_sizes, int n_in,
                              void* d_out, int out_size) {
    const float* x     = (const float*)d_in[0];
    const float* W_S   = (const float*)d_in[1];
    const float* W_NS  = (const float*)d_in[2];
    const float* W_out = (const float*)d_in[3];
    float* out = (float*)d_out;
    (void)in_sizes; (void)n_in; (void)out_size;

    const int gemm_smem = 36864 * 2;   // 73728 B
    const int attn_smem = 18432 * 2;   // 36864 B

    cudaFuncSetAttribute(fused_qkv,   cudaFuncAttributeMaxDynamicSharedMemorySize, gemm_smem);
    cudaFuncSetAttribute(gemm_out,    cudaFuncAttributeMaxDynamicSharedMemorySize, gemm_smem);
    cudaFuncSetAttribute(attn_kernel, cudaFuncAttributeMaxDynamicSharedMemorySize, attn_smem);

    // 0) prep: x/W_S/W_out -> fp16 permuted
    prep_x<<<512, 256>>>(x);
    prep_tr<<<dim3(3 * DM / 32, DM / 32), 256>>>(W_S, 0);
    prep_tr<<<dim3(DM / 32, DM / 32), 256>>>(W_out, 1);

    // 1+2) fused: 640 GEMM tiles + 768 NS k-quarter blocks (5:6 interleave)
    fused_qkv<<<1408, 256, gemm_smem>>>(x, W_NS);
    ns_finalize<<<192, 256>>>();

    // 2b) repack V (transpose + token 16-blk permute)
    repack_Vt<<<dim3(LK / 32, DM / 32), 256>>>();

    // 3) attention, split-KV x2: 544 half-range CTAs, longest first
    attn_kernel<<<544, 256, attn_smem>>>();
    combine_attn<<<272, 256>>>();

    // 4) output projection, full K, direct stores
    gemm_out<<<dim3(1024 / 128, (LQ + 127) / 128), 256, gemm_smem>>>(out);
}